// round 3
// baseline (speedup 1.0000x reference)
#include <cuda_runtime.h>

#define D_MODEL 64
#define N_CODES 2048

// scratch (no device allocation allowed)
__device__ float  g_colsum[N_CODES];
__device__ double g_losssum;

// ---------------------------------------------------------------------------
// Kernel 0: colsum[k] = sum_d emb[k][d]^2, serial mul+add; zero loss accum.
// (unchanged from R2 — proven bit-compatible)
// ---------------------------------------------------------------------------
__global__ void prep_kernel(const float* __restrict__ emb) {
    int k = blockIdx.x * blockDim.x + threadIdx.x;
    if (k == 0) g_losssum = 0.0;
    if (k < N_CODES) {
        const float* e = emb + (size_t)k * D_MODEL;
        float s = 0.f;
        #pragma unroll
        for (int d = 0; d < D_MODEL; ++d)
            s = __fadd_rn(s, __fmul_rn(e[d], e[d]));
        g_colsum[k] = s;
    }
}

// ---------------------------------------------------------------------------
// Main kernel: one thread per row. IDENTICAL to R2 except the dot product is
// computed exactly (fp64 serial DFMA; products of f32 pairs are exact in f64)
// and rounded once to f32 — i.e. the correctly-rounded fp32 dot. The epilogue
// double-rounding fl(fl(rsum-2*dot)+cs) and lowest-index tiebreak unchanged.
// ---------------------------------------------------------------------------
__global__ void __launch_bounds__(128)
vq_main_kernel(const float* __restrict__ X, const float* __restrict__ E,
               float* __restrict__ out, int NR, int has_extras) {
    extern __shared__ float sh[];
    float4* Es4 = (float4*)sh;          // [128 codes][16 quads]  (row-major)
    float*  cs  = sh + 128 * D_MODEL;   // [128] colsums

    const int tid = threadIdx.x;
    const long row = (long)blockIdx.x * 128 + tid;

    // ---- load this thread's x row into registers (64 floats) ----
    float4 xr[16];
    const float4* Xg = (const float4*)X + row * 16;
    #pragma unroll
    for (int q = 0; q < 16; ++q) xr[q] = Xg[q];

    // fp64 copies of x for the exact dot
    double xd[64];
    #pragma unroll
    for (int q = 0; q < 16; ++q) {
        xd[4 * q + 0] = (double)xr[q].x;
        xd[4 * q + 1] = (double)xr[q].y;
        xd[4 * q + 2] = (double)xr[q].z;
        xd[4 * q + 3] = (double)xr[q].w;
    }

    // ---- rowsum: serial mul+add over d = 0..63 (bit-matches reference) ----
    float rsum = 0.f;
    #pragma unroll
    for (int q = 0; q < 16; ++q) {
        rsum = __fadd_rn(rsum, __fmul_rn(xr[q].x, xr[q].x));
        rsum = __fadd_rn(rsum, __fmul_rn(xr[q].y, xr[q].y));
        rsum = __fadd_rn(rsum, __fmul_rn(xr[q].z, xr[q].z));
        rsum = __fadd_rn(rsum, __fmul_rn(xr[q].w, xr[q].w));
    }

    float bestv = __int_as_float(0x7f800000);   // +inf
    int   besti = 0;

    for (int t = 0; t < N_CODES / 128; ++t) {
        __syncthreads();   // previous tile fully consumed
        const float4* Eg = (const float4*)E + (size_t)t * 128 * 16;
        #pragma unroll
        for (int it = 0; it < 16; ++it)
            Es4[tid + it * 128] = Eg[tid + it * 128];
        cs[tid] = g_colsum[t * 128 + tid];
        __syncthreads();

        #pragma unroll 1
        for (int c0 = 0; c0 < 128; c0 += 4) {
            double a0 = 0.0, a1 = 0.0, a2 = 0.0, a3 = 0.0;
            #pragma unroll
            for (int q = 0; q < 16; ++q) {
                const float4 e0 = Es4[(c0 + 0) * 16 + q];  // broadcast LDS
                const float4 e1 = Es4[(c0 + 1) * 16 + q];
                const float4 e2 = Es4[(c0 + 2) * 16 + q];
                const float4 e3 = Es4[(c0 + 3) * 16 + q];
                const double x0 = xd[4 * q + 0], x1 = xd[4 * q + 1];
                const double x2 = xd[4 * q + 2], x3 = xd[4 * q + 3];
                a0 = __fma_rn(x0, (double)e0.x, a0);
                a0 = __fma_rn(x1, (double)e0.y, a0);
                a0 = __fma_rn(x2, (double)e0.z, a0);
                a0 = __fma_rn(x3, (double)e0.w, a0);
                a1 = __fma_rn(x0, (double)e1.x, a1);
                a1 = __fma_rn(x1, (double)e1.y, a1);
                a1 = __fma_rn(x2, (double)e1.z, a1);
                a1 = __fma_rn(x3, (double)e1.w, a1);
                a2 = __fma_rn(x0, (double)e2.x, a2);
                a2 = __fma_rn(x1, (double)e2.y, a2);
                a2 = __fma_rn(x2, (double)e2.z, a2);
                a2 = __fma_rn(x3, (double)e2.w, a2);
                a3 = __fma_rn(x0, (double)e3.x, a3);
                a3 = __fma_rn(x1, (double)e3.y, a3);
                a3 = __fma_rn(x2, (double)e3.z, a3);
                a3 = __fma_rn(x3, (double)e3.w, a3);
            }
            const int cb = t * 128 + c0;
            float w, dotf;
            dotf = (float)a0;   // correctly-rounded fp32 dot
            w = __fadd_rn(__fmaf_rn(-2.f, dotf, rsum), cs[c0 + 0]);
            if (w < bestv) { bestv = w; besti = cb + 0; }
            dotf = (float)a1;
            w = __fadd_rn(__fmaf_rn(-2.f, dotf, rsum), cs[c0 + 1]);
            if (w < bestv) { bestv = w; besti = cb + 1; }
            dotf = (float)a2;
            w = __fadd_rn(__fmaf_rn(-2.f, dotf, rsum), cs[c0 + 2]);
            if (w < bestv) { bestv = w; besti = cb + 2; }
            dotf = (float)a3;
            w = __fadd_rn(__fmaf_rn(-2.f, dotf, rsum), cs[c0 + 3]);
            if (w < bestv) { bestv = w; besti = cb + 3; }
        }
    }

    // ---- fused gather: z_q_st = fl(ze + fl(e - ze)), fp64 loss partial ----
    const float4* Ee = (const float4*)E + (size_t)besti * 16;
    float4* Og = (float4*)out + row * 16;
    double ls = 0.0;
    #pragma unroll
    for (int q = 0; q < 16; ++q) {
        const float4 ze = xr[q];
        const float4 ev = Ee[q];
        float dx = __fsub_rn(ev.x, ze.x);
        float dy = __fsub_rn(ev.y, ze.y);
        float dz = __fsub_rn(ev.z, ze.z);
        float dw = __fsub_rn(ev.w, ze.w);
        float4 o;
        o.x = __fadd_rn(ze.x, dx);
        o.y = __fadd_rn(ze.y, dy);
        o.z = __fadd_rn(ze.z, dz);
        o.w = __fadd_rn(ze.w, dw);
        Og[q] = o;
        ls += (double)dx * dx + (double)dy * dy
            + (double)dz * dz + (double)dw * dw;
    }
    #pragma unroll
    for (int off = 16; off; off >>= 1)
        ls += __shfl_down_sync(0xffffffffu, ls, off);
    if ((tid & 31) == 0) atomicAdd(&g_losssum, ls);

    if (has_extras)
        out[(size_t)NR * D_MODEL + 1 + row] = (float)besti;
}

// ---------------------------------------------------------------------------
__global__ void finalize_kernel(float* __restrict__ out, int NR) {
    double m = g_losssum / (double)((size_t)NR * D_MODEL);
    float mf = (float)m;
    out[(size_t)NR * D_MODEL] = __fadd_rn(__fmul_rn(0.25f, mf), mf);
}

// ---------------------------------------------------------------------------
extern "C" void kernel_launch(void* const* d_in, const int* in_sizes, int n_in,
                              void* d_out, int out_size) {
    (void)n_in;
    const float* ze;
    const float* emb;
    int nz;
    if (in_sizes[0] >= in_sizes[1]) {
        ze = (const float*)d_in[0]; emb = (const float*)d_in[1]; nz = in_sizes[0];
    } else {
        ze = (const float*)d_in[1]; emb = (const float*)d_in[0]; nz = in_sizes[1];
    }
    const int NR = nz / D_MODEL;          // 131072 rows

    float* out = (float*)d_out;
    const int has_extras = (out_size >= NR * D_MODEL + 1 + NR) ? 1 : 0;

    const int SMEM_BYTES = 128 * D_MODEL * 4 + 128 * 4;   // 33280

    prep_kernel<<<(N_CODES + 127) / 128, 128>>>(emb);
    vq_main_kernel<<<NR / 128, 128, SMEM_BYTES>>>(ze, emb, out, NR, has_extras);
    if (out_size > NR * D_MODEL)
        finalize_kernel<<<1, 1>>>(out, NR);
}